// round 12
// baseline (speedup 1.0000x reference)
#include <cuda_runtime.h>

// ArcFaceLoss: N=8192 rows, C=32000 classes, S=30, M=0.5
// Warp-per-row persistent kernel: 1024 CTAs x 8 warps = 8192 warps, 1 row each.
// No __syncthreads in the streaming path; warp-shuffle reduce only.
// loss_row = log( sum_j exp(S*clamp(pred_j)) - exp(S*tc) + exp(S*tm) ) - S*tm

#define NROWS 8192
#define NCOLS 32000
#define NV4   (NCOLS / 4)   // 8000 float4 per row; 250 per lane
#define TPB   256
#define GRID  1024          // GRID * 8 warps == NROWS

__device__ float        g_row_loss[NROWS];
__device__ unsigned int g_done = 0;

typedef unsigned long long u64;

__device__ __forceinline__ u64 pk2(float lo, float hi) {
    u64 r; asm("mov.b64 %0, {%1, %2};" : "=l"(r) : "f"(lo), "f"(hi)); return r;
}
__device__ __forceinline__ void upk2(u64 v, float& lo, float& hi) {
    asm("mov.b64 {%0, %1}, %2;" : "=f"(lo), "=f"(hi) : "l"(v));
}
__device__ __forceinline__ void upk2i(u64 v, int& lo, int& hi) {
    asm("mov.b64 {%0, %1}, %2;" : "=r"(lo), "=r"(hi) : "l"(v));
}
__device__ __forceinline__ u64 add2(u64 a, u64 b) {
    u64 d; asm("add.rn.f32x2 %0, %1, %2;" : "=l"(d) : "l"(a), "l"(b)); return d;
}
__device__ __forceinline__ u64 fma2(u64 a, u64 b, u64 c) {
    u64 d; asm("fma.rn.f32x2 %0, %1, %2, %3;" : "=l"(d) : "l"(a), "l"(b), "l"(c)); return d;
}

__global__ void __launch_bounds__(TPB, 8) arcface_fused_kernel(
    const float* __restrict__ pred, const int* __restrict__ tgt,
    float* __restrict__ out)
{
    __shared__ float s_partial[TPB / 32];
    __shared__ int   s_last;

    const int tid  = threadIdx.x;
    const int lane = tid & 31;
    const int wid  = tid >> 5;
    const int row  = blockIdx.x * 8 + wid;     // one full row per warp

    // dtype auto-detect (uniform): int64-LE high words are 0
    bool is64 = true;
    #pragma unroll
    for (int k = 0; k < 16; ++k) is64 = is64 && (tgt[2 * k + 1] == 0);

    const int t = is64 ? __ldg(&tgt[2 * row]) : __ldg(&tgt[row]);
    // prefetch target-column value (uniform across warp; completes under loop)
    const float tcraw = __ldg(&pred[(size_t)row * NCOLS + t]);

    const float Kf    = 43.2808512266689f;      // S * log2(e)
    const float MAGIC = 12582912.0f;            // 1.5 * 2^23
    const u64 K2   = pk2(Kf, Kf);
    const u64 MG2  = pk2(MAGIC, MAGIC);
    const u64 M1_2 = pk2(-1.0f, -1.0f);
    const u64 C3_2 = pk2(0.0555041086f, 0.0555041086f);
    const u64 C2_2 = pk2(0.2402265070f, 0.2402265070f);
    const u64 C1_2 = pk2(0.6931471806f, 0.6931471806f);
    const u64 ONE2 = pk2(1.0f, 1.0f);

    const float4* rowp = reinterpret_cast<const float4*>(pred + (size_t)row * NCOLS);

    u64 accA = pk2(0.0f, 0.0f);
    u64 accB = pk2(0.0f, 0.0f);

    #pragma unroll 5
    for (int j = lane; j < NV4; j += 32) {     // 250 iterations per lane
        float4 v = __ldcs(rowp + j);
        float c0 = fminf(fmaxf(v.x, -1.0f), 1.0f);
        float c1 = fminf(fmaxf(v.y, -1.0f), 1.0f);
        float c2 = fminf(fmaxf(v.z, -1.0f), 1.0f);
        float c3 = fminf(fmaxf(v.w, -1.0f), 1.0f);
        u64 cA = pk2(c0, c1);
        u64 cB = pk2(c2, c3);

        // z = c*K + MAGIC (low mantissa bits hold round(c*K))
        u64 zA = fma2(cA, K2, MG2);
        u64 zB = fma2(cB, K2, MG2);
        // -n = -z + MAGIC
        u64 nnA = fma2(zA, M1_2, MG2);
        u64 nnB = fma2(zB, M1_2, MG2);
        // f = c*K - n in [-0.5, 0.5]
        u64 fA = fma2(cA, K2, nnA);
        u64 fB = fma2(cB, K2, nnB);
        // 2^f degree-3 poly
        u64 pA = fma2(C3_2, fA, C2_2);
        u64 pB = fma2(C3_2, fB, C2_2);
        pA = fma2(pA, fA, C1_2);
        pB = fma2(pB, fB, C1_2);
        pA = fma2(pA, fA, ONE2);
        pB = fma2(pB, fB, ONE2);

        int i0, i1, i2, i3;
        upk2i(zA, i0, i1);
        upk2i(zB, i2, i3);
        float q0, q1, q2, q3;
        upk2(pA, q0, q1);
        upk2(pB, q2, q3);
        // exponent injection: (i<<23) + bits(p)
        float e0 = __int_as_float((i0 << 23) + __float_as_int(q0));
        float e1 = __int_as_float((i1 << 23) + __float_as_int(q1));
        float e2 = __int_as_float((i2 << 23) + __float_as_int(q2));
        float e3 = __int_as_float((i3 << 23) + __float_as_int(q3));

        accA = add2(accA, pk2(e0, e1));
        accB = add2(accB, pk2(e2, e3));
    }

    u64 accT = add2(accA, accB);
    float sl, sh;
    upk2(accT, sl, sh);
    float acc = sl + sh;

    // warp-only deterministic reduction
    #pragma unroll
    for (int o = 16; o > 0; o >>= 1)
        acc += __shfl_down_sync(0xffffffffu, acc, o);

    if (lane == 0) {
        const float cosM = 0.87758256189037276f;   // cos(0.5)
        const float sinM = 0.47942553860420301f;   // sin(0.5)
        const float MM   = 0.23971276930210150f;   // sin(0.5)*0.5
        const float THR  = -0.87758256189037276f;  // cos(pi-0.5)
        const float L2E  = 1.44269504088896340f;

        float tc = fminf(fmaxf(tcraw, -1.0f), 1.0f);
        float tm = (tc > THR)
                 ? fmaf(tc, cosM, -sqrtf(fmaxf(1.0f - tc * tc, 0.0f)) * sinM)
                 : (tc - MM);

        float sum2 = acc - exp2f(30.0f * L2E * tc) + exp2f(30.0f * L2E * tm);
        g_row_loss[row] = logf(sum2) - 30.0f * tm;
        __threadfence();   // make this warp's row loss GPU-visible pre-arrival
    }

    __syncthreads();       // single block sync: all 8 rows of this CTA done

    // ── deterministic final reduction by the last-arriving CTA ──
    if (tid == 0) {
        unsigned int old = atomicAdd(&g_done, 1u);
        s_last = (old == GRID - 1) ? 1 : 0;
    }
    __syncthreads();
    if (s_last) {
        __threadfence();
        float s = 0.0f;
        #pragma unroll
        for (int k = 0; k < NROWS / TPB; ++k)
            s += g_row_loss[tid + k * TPB];
        #pragma unroll
        for (int o = 16; o > 0; o >>= 1)
            s += __shfl_down_sync(0xffffffffu, s, o);
        if ((tid & 31) == 0) s_partial[tid >> 5] = s;
        __syncthreads();
        if (tid == 0) {
            float tot = 0.0f;
            #pragma unroll
            for (int w = 0; w < TPB / 32; ++w) tot += s_partial[w];
            out[0] = tot * (1.0f / (float)NROWS);
            g_done = 0;   // reset for next graph replay
        }
    }
}

extern "C" void kernel_launch(void* const* d_in, const int* in_sizes, int n_in,
                              void* d_out, int out_size)
{
    const float* pred = (const float*)d_in[0];
    const int*   tgt  = (const int*)d_in[1];
    float*       out  = (float*)d_out;

    arcface_fused_kernel<<<GRID, TPB>>>(pred, tgt, out);
}